// round 5
// baseline (speedup 1.0000x reference)
#include <cuda_runtime.h>

// Sparse ConvTranspose3d on GB300 (sm_103a)
//   out[r,:] = bias + sum_{(k,n): out_index[k,n]==r} feats[n,:] @ weight[k,:,:]^T
//
// Key insight: the kernel map is ~bijective; ~95% of output rows have exactly
// ONE contributor. Precompute per-row contributor counts (6.5MB, L2-resident);
// in the epilogue use plain stores (acc+bias) for count==1 rows (no RMW read),
// atomics only for the rare multi-contributor rows.
//
// Launch order: zero counts -> count -> bias init -> GEMM+scatter.

#define CIN    64
#define COUT   64
#define TILE_N 128
#define KCHUNK 9
#define MAX_ROWS (60000 * 27)

__device__ int g_counts[MAX_ROWS];

// ---------------------------------------------------------------- counts ----
__global__ void zero_counts_kernel(int n_out) {
    int i = blockIdx.x * blockDim.x + threadIdx.x;
    int4* p = reinterpret_cast<int4*>(g_counts);
    if (i < (n_out + 3) / 4) p[i] = make_int4(0, 0, 0, 0);
}

__global__ void count_kernel(const int* __restrict__ out_index, int total) {
    int i = blockIdx.x * blockDim.x + threadIdx.x;
    if (i < total) atomicAdd(&g_counts[out_index[i]], 1);
}

// ------------------------------------------------------------- bias init ----
__global__ void bias_init_kernel(float4* __restrict__ out4,
                                 const float4* __restrict__ bias4,
                                 int total4) {
    int i = blockIdx.x * blockDim.x + threadIdx.x;
    if (i < total4) out4[i] = bias4[i & 15];   // 64 floats per row = 16 chunks
}

// ------------------------------------------------------------- main GEMM ----
__device__ __forceinline__ void fma2(double& d, double a, double b) {
    asm("fma.rn.f32x2 %0, %1, %2, %0;" : "+l"(*(unsigned long long*)&d)
        : "l"(*(unsigned long long*)&a), "l"(*(unsigned long long*)&b));
}

__global__ void __launch_bounds__(256, 2) spconvt_gemm_scatter_kernel(
    const float* __restrict__ feats,     // [N, CIN]
    const float* __restrict__ weight,    // [KV, COUT, CIN]
    const float* __restrict__ bias,      // [COUT]
    const int*   __restrict__ out_index, // [KV, N]
    float*       __restrict__ out,       // [n_out, COUT]
    int N, int KV)
{
    extern __shared__ float smem[];
    float (*As)[CIN] = reinterpret_cast<float (*)[CIN]>(smem);   // 128x64 = 32KB
    float* Wbuf = smem + TILE_N * CIN;                            // 2x(64x64) = 32KB

    const int tid = threadIdx.x;
    const int n0  = blockIdx.x * TILE_N;
    const int k0  = blockIdx.y * KCHUNK;

    // ---- Load A tile once ----
    const float4* f4 = reinterpret_cast<const float4*>(feats);
    #pragma unroll
    for (int t = 0; t < 8; t++) {
        int idx = tid + t * 256;          // 0..2047
        int p = idx >> 4;
        int q = idx & 15;
        int n = n0 + p;
        float4 v = make_float4(0.f, 0.f, 0.f, 0.f);
        if (n < N) v = f4[(size_t)n * 16 + q];
        *reinterpret_cast<float4*>(&As[p][q * 4]) = v;
    }

    // ---- cp.async W loader, chunk-swizzled: phys q = q ^ ((c>>2)&15) ----
    auto cpW = [&](int k, int b) {
        const char* src = reinterpret_cast<const char*>(weight + (size_t)k * COUT * CIN);
        float* dstbase = Wbuf + b * COUT * CIN;
        #pragma unroll
        for (int j = 0; j < 4; j++) {
            int idx = tid + 256 * j;      // 0..1023 float4s
            int c = idx >> 4;
            int q = idx & 15;
            int qs = q ^ ((c >> 2) & 15);
            unsigned dst = (unsigned)__cvta_generic_to_shared(dstbase + c * CIN + qs * 4);
            asm volatile("cp.async.cg.shared.global [%0], [%1], 16;\n"
                         :: "r"(dst), "l"(src + (size_t)idx * 16));
        }
        asm volatile("cp.async.commit_group;\n");
    };

    cpW(k0, 0);
    asm volatile("cp.async.wait_group 0;\n" ::: "memory");
    __syncthreads();

    const int tc = tid & 15;
    const int tp = tid >> 4;
    const int c0 = tc * 4;
    const int p0 = tp * 8;

    int buf = 0;
    for (int kk = 0; kk < KCHUNK; kk++) {
        int k = k0 + kk;
        if (k >= KV) break;

        if (kk + 1 < KCHUNK && k + 1 < KV) cpW(k + 1, buf ^ 1);

        // prefetch output row ids
        int rr[8];
        const int* oi = out_index + (size_t)k * N + n0 + p0;
        #pragma unroll
        for (int pj = 0; pj < 8; pj++)
            rr[pj] = (n0 + p0 + pj < N) ? oi[pj] : -1;

        const float* Wc = Wbuf + buf * COUT * CIN;

        // packed accumulators: lo lane = even cin, hi lane = odd cin
        double acc2[8][4];
        #pragma unroll
        for (int a = 0; a < 8; a++)
            #pragma unroll
            for (int b2 = 0; b2 < 4; b2++) acc2[a][b2] = 0.0;

        const int qsx = tc;
        #pragma unroll 4
        for (int q = 0; q < 16; q++) {
            int qs = q ^ qsx;
            double2 wv[4];
            #pragma unroll
            for (int cj = 0; cj < 4; cj++)
                wv[cj] = *reinterpret_cast<const double2*>(&Wc[(c0 + cj) * CIN + qs * 4]);

            #pragma unroll
            for (int pj = 0; pj < 8; pj++) {
                double2 av = *reinterpret_cast<const double2*>(&As[p0 + pj][q * 4]);
                #pragma unroll
                for (int cj = 0; cj < 4; cj++) {
                    fma2(acc2[pj][cj], av.x, wv[cj].x);
                    fma2(acc2[pj][cj], av.y, wv[cj].y);
                }
            }
        }

        // ---- epilogue: count==1 -> plain store of acc+bias; else atomic ----
        int cnt[8];
        #pragma unroll
        for (int pj = 0; pj < 8; pj++)
            cnt[pj] = (rr[pj] >= 0) ? __ldg(&g_counts[rr[pj]]) : 0;

        float4 b4 = *reinterpret_cast<const float4*>(bias + c0);  // L1-hot

        #pragma unroll
        for (int pj = 0; pj < 8; pj++) {
            if (rr[pj] >= 0) {
                float2 f0 = *reinterpret_cast<float2*>(&acc2[pj][0]);
                float2 f1 = *reinterpret_cast<float2*>(&acc2[pj][1]);
                float2 f2 = *reinterpret_cast<float2*>(&acc2[pj][2]);
                float2 f3 = *reinterpret_cast<float2*>(&acc2[pj][3]);
                float r0 = f0.x + f0.y, r1 = f1.x + f1.y;
                float r2 = f2.x + f2.y, r3 = f3.x + f3.y;
                float* dst = out + (size_t)rr[pj] * COUT + c0;   // 16B aligned
                if (cnt[pj] == 1) {
                    *reinterpret_cast<float4*>(dst) =
                        make_float4(r0 + b4.x, r1 + b4.y, r2 + b4.z, r3 + b4.w);
                } else {
                    asm volatile("red.global.add.v4.f32 [%0], {%1, %2, %3, %4};"
                                 :: "l"(dst), "f"(r0), "f"(r1), "f"(r2), "f"(r3)
                                 : "memory");
                }
            }
        }

        asm volatile("cp.async.wait_group 0;\n" ::: "memory");
        __syncthreads();
        buf ^= 1;
    }
}

extern "C" void kernel_launch(void* const* d_in, const int* in_sizes, int n_in,
                              void* d_out, int out_size) {
    const float* feats     = (const float*)d_in[0];   // [N, 64]
    const float* weight    = (const float*)d_in[1];   // [KV, 64, 64]
    const float* bias      = (const float*)d_in[2];   // [64]
    const int*   out_index = (const int*)d_in[3];     // [KV, N]
    float* out = (float*)d_out;                        // [n_out, 64]

    int N  = in_sizes[0] / CIN;
    int KV = in_sizes[1] / (COUT * CIN);
    int n_out = out_size / COUT;
    int total_idx = in_sizes[3];                      // KV * N

    // 1) zero counts (int4 stores)
    int z4 = (n_out + 3) / 4;
    zero_counts_kernel<<<(z4 + 255) / 256, 256>>>(n_out);

    // 2) count contributors per output row (table is L2-resident)
    count_kernel<<<(total_idx + 255) / 256, 256>>>(out_index, total_idx);

    // 3) out = bias broadcast
    int total4 = out_size / 4;
    bias_init_kernel<<<(total4 + 255) / 256, 256>>>((float4*)out,
                                                    (const float4*)bias, total4);

    // 4) persistent-over-k GEMM + split scatter
    const int smem_bytes = (TILE_N * CIN + 2 * COUT * CIN) * sizeof(float);  // 64KB
    cudaFuncSetAttribute(spconvt_gemm_scatter_kernel,
                         cudaFuncAttributeMaxDynamicSharedMemorySize, smem_bytes);
    dim3 grid((N + TILE_N - 1) / TILE_N, (KV + KCHUNK - 1) / KCHUNK);
    spconvt_gemm_scatter_kernel<<<grid, 256, smem_bytes>>>(
        feats, weight, bias, out_index, out, N, KV);
}

// round 7
// speedup vs baseline: 2.2746x; 2.2746x over previous
#include <cuda_runtime.h>
#include <cstdint>

// Sparse ConvTranspose3d on GB300 (sm_103a) — tensor cores via mma.sync tf32
// (tcgen05 is unavailable: harness PTX target is sm_103 without the 'a' feature).
//
//   out[r,:] = bias + sum_{(k,n): out_index[k,n]==r} feats[n,:] @ weight[k,:,:]^T
//
// Per (k, 128-pt tile): D[128x64] = A[128x64] * W[k][64x64]^T with
// mma.sync.m16n8k8.row.col.f32.tf32.tf32.f32. W row-major [cout][cin] IS the
// col-major B operand. SMEM tiles padded to stride 68 floats -> conflict-free
// fragment loads. Inputs rounded with cvt.rna.tf32 at SMEM-fill.
// Epilogue: counts split — count==1 rows get plain st.v2 of acc+bias,
// others red.global.add.v2.f32 onto conditionally bias-initialized rows.

#define CIN    64
#define COUT   64
#define TILE_N 128
#define KCHUNK 9
#define LDA    68          // padded row stride (floats)
#define MAX_ROWS (60000 * 27)

__device__ int g_counts[MAX_ROWS];

// ---------------------------------------------------------------- pre-pass ----
__global__ void zero_counts_kernel(int n4) {
    int i = blockIdx.x * blockDim.x + threadIdx.x;
    if (i < n4) reinterpret_cast<int4*>(g_counts)[i] = make_int4(0, 0, 0, 0);
}
__global__ void count_kernel(const int* __restrict__ oi, int total) {
    int i = blockIdx.x * blockDim.x + threadIdx.x;
    if (i < total) atomicAdd(&g_counts[oi[i]], 1);
}
// init rows whose count != 1 (count==0: pure bias; count>=2: bias base for atomics)
__global__ void cond_bias_init_kernel(const float4* __restrict__ bias4,
                                      float4* __restrict__ out4, int n_out) {
    int r = blockIdx.x * blockDim.x + threadIdx.x;
    if (r < n_out && g_counts[r] != 1) {
        #pragma unroll
        for (int j = 0; j < 16; j++) out4[(size_t)r * 16 + j] = bias4[j];
    }
}

// ---------------------------------------------------------------- helpers ----
__device__ __forceinline__ uint32_t to_tf32(float f) {
    uint32_t u;
    asm("cvt.rna.tf32.f32 %0, %1;" : "=r"(u) : "f"(f));
    return u;
}
__device__ __forceinline__ uint32_t f2u(float f) { return __float_as_uint(f); }

__device__ __forceinline__ void mma_tf32(float c[4], const uint32_t a[4],
                                         uint32_t b0, uint32_t b1) {
    asm volatile(
        "mma.sync.aligned.m16n8k8.row.col.f32.tf32.tf32.f32 "
        "{%0,%1,%2,%3}, {%4,%5,%6,%7}, {%8,%9}, {%0,%1,%2,%3};"
        : "+f"(c[0]), "+f"(c[1]), "+f"(c[2]), "+f"(c[3])
        : "r"(a[0]), "r"(a[1]), "r"(a[2]), "r"(a[3]), "r"(b0), "r"(b1));
}

// ------------------------------------------------------------- main kernel ----
__global__ void __launch_bounds__(128, 2) spconvt_mma_kernel(
    const float* __restrict__ feats,     // [N, 64]
    const float* __restrict__ weight,    // [27, 64, 64]
    const float* __restrict__ bias,      // [64]
    const int*   __restrict__ out_index, // [27, N]
    float*       __restrict__ out,       // [n_out, 64]
    int N, int KV)
{
    extern __shared__ float smem[];
    float* As = smem;                        // 128 x 68
    float* Wb = smem + TILE_N * LDA;         // 2 x (64 x 68)

    const int tid  = threadIdx.x;
    const int w    = tid >> 5;
    const int lane = tid & 31;
    const int g    = lane >> 2;              // group id 0..7
    const int t    = lane & 3;               // thread-in-group 0..3
    const int n0   = blockIdx.x * TILE_N;
    const int k0   = blockIdx.y * KCHUNK;

    // ---- A tile: LDG -> cvt.rna.tf32 -> padded SMEM ----
    const float4* f4 = reinterpret_cast<const float4*>(feats);
    #pragma unroll
    for (int j = 0; j < 16; j++) {
        int idx = tid + 128 * j;              // 0..2047 float4s
        int p = idx >> 4, q = idx & 15;
        int n = n0 + p;
        float4 v = make_float4(0.f, 0.f, 0.f, 0.f);
        if (n < N) v = f4[(size_t)n * 16 + q];
        float* dst = As + p * LDA + q * 4;
        dst[0] = __uint_as_float(to_tf32(v.x));
        dst[1] = __uint_as_float(to_tf32(v.y));
        dst[2] = __uint_as_float(to_tf32(v.z));
        dst[3] = __uint_as_float(to_tf32(v.w));
    }
    // ---- W[k0] -> buf0 ----
    {
        const float4* ws = reinterpret_cast<const float4*>(weight + (size_t)k0 * COUT * CIN);
        #pragma unroll
        for (int j = 0; j < 8; j++) {
            int idx = tid + 128 * j;          // 0..1023
            int c = idx >> 4, q = idx & 15;
            float4 v = ws[idx];
            float* dst = Wb + c * LDA + q * 4;
            dst[0] = __uint_as_float(to_tf32(v.x));
            dst[1] = __uint_as_float(to_tf32(v.y));
            dst[2] = __uint_as_float(to_tf32(v.z));
            dst[3] = __uint_as_float(to_tf32(v.w));
        }
    }

    // per-thread bias pairs: bias[8*nt + 2t], bias[8*nt + 2t + 1]
    float2 b2[8];
    #pragma unroll
    for (int nt = 0; nt < 8; nt++)
        b2[nt] = __ldg(reinterpret_cast<const float2*>(bias) + nt * 4 + t);

    __syncthreads();

    const int p0 = 32 * w + g;               // first of 4 owned point rows
    int buf = 0;

    for (int kk = 0; kk < KCHUNK; kk++) {
        int k = k0 + kk;
        if (k >= KV) break;
        bool more = (kk + 1 < KCHUNK) && (k + 1 < KV);

        // prefetch W[k+1] into regs (latency hidden under the MMA loop)
        float4 wreg[8];
        if (more) {
            const float4* ws = reinterpret_cast<const float4*>(
                weight + (size_t)(k + 1) * COUT * CIN);
            #pragma unroll
            for (int j = 0; j < 8; j++) wreg[j] = ws[tid + 128 * j];
        }
        // prefetch scatter metadata for the 4 owned rows
        int rrv[4], cntv[4];
        #pragma unroll
        for (int j = 0; j < 4; j++) {
            int n = n0 + p0 + 8 * j;
            rrv[j]  = (n < N) ? __ldg(out_index + (size_t)k * N + n) : -1;
            cntv[j] = (rrv[j] >= 0) ? __ldg(&g_counts[rrv[j]]) : 0;
        }

        const float* Wc = Wb + buf * (COUT * LDA);

        float acc[2][8][4];
        #pragma unroll
        for (int mt = 0; mt < 2; mt++)
            #pragma unroll
            for (int nt = 0; nt < 8; nt++)
                #pragma unroll
                for (int x = 0; x < 4; x++) acc[mt][nt][x] = 0.f;

        #pragma unroll
        for (int kc = 0; kc < 8; kc++) {
            const int kb = kc * 8;
            uint32_t a[2][4];
            #pragma unroll
            for (int mt = 0; mt < 2; mt++) {
                int r0 = 32 * w + 16 * mt + g;
                a[mt][0] = f2u(As[(r0)     * LDA + kb + t]);
                a[mt][1] = f2u(As[(r0 + 8) * LDA + kb + t]);
                a[mt][2] = f2u(As[(r0)     * LDA + kb + t + 4]);
                a[mt][3] = f2u(As[(r0 + 8) * LDA + kb + t + 4]);
            }
            #pragma unroll
            for (int nt = 0; nt < 8; nt++) {
                int c = 8 * nt + g;
                uint32_t b0 = f2u(Wc[c * LDA + kb + t]);
                uint32_t b1 = f2u(Wc[c * LDA + kb + t + 4]);
                mma_tf32(acc[0][nt], a[0], b0, b1);
                mma_tf32(acc[1][nt], a[1], b0, b1);
            }
        }

        // stage W[k+1] into the other buffer (other warps may still read buf)
        if (more) {
            float* dstb = Wb + (buf ^ 1) * (COUT * LDA);
            #pragma unroll
            for (int j = 0; j < 8; j++) {
                int idx = tid + 128 * j;
                int c = idx >> 4, q = idx & 15;
                float* dst = dstb + c * LDA + q * 4;
                dst[0] = __uint_as_float(to_tf32(wreg[j].x));
                dst[1] = __uint_as_float(to_tf32(wreg[j].y));
                dst[2] = __uint_as_float(to_tf32(wreg[j].z));
                dst[3] = __uint_as_float(to_tf32(wreg[j].w));
            }
        }

        // ---- scatter epilogue ----
        // owned rows: j=0..3 -> point p0+8j = 32w + 16*(j>>1) + g + 8*(j&1)
        // values: acc[j>>1][nt][(j&1)*2 + {0,1}] at cols 8*nt + 2t + {0,1}
        #pragma unroll
        for (int j = 0; j < 4; j++) {
            if (rrv[j] < 0) continue;
            const int mt = j >> 1, hi = (j & 1) * 2;
            float* dst = out + (size_t)rrv[j] * COUT + 2 * t;
            if (cntv[j] == 1) {
                #pragma unroll
                for (int nt = 0; nt < 8; nt++) {
                    float2 v = make_float2(acc[mt][nt][hi]     + b2[nt].x,
                                           acc[mt][nt][hi + 1] + b2[nt].y);
                    *reinterpret_cast<float2*>(dst + 8 * nt) = v;
                }
            } else {
                #pragma unroll
                for (int nt = 0; nt < 8; nt++) {
                    asm volatile("red.global.add.v2.f32 [%0], {%1, %2};"
                                 :: "l"(dst + 8 * nt),
                                    "f"(acc[mt][nt][hi]), "f"(acc[mt][nt][hi + 1])
                                 : "memory");
                }
            }
        }

        __syncthreads();      // all warps done with buf; W[k+1] in buf^1 visible
        buf ^= 1;
    }
}

extern "C" void kernel_launch(void* const* d_in, const int* in_sizes, int n_in,
                              void* d_out, int out_size) {
    const float* feats     = (const float*)d_in[0];   // [N, 64]
    const float* weight    = (const float*)d_in[1];   // [27, 64, 64]
    const float* bias      = (const float*)d_in[2];   // [64]
    const int*   out_index = (const int*)d_in[3];     // [27, N]
    float* out = (float*)d_out;                        // [n_out, 64]

    int N  = in_sizes[0] / CIN;
    int KV = in_sizes[1] / (COUT * CIN);
    int n_out = out_size / COUT;
    int total_idx = in_sizes[3];                       // KV * N

    int z4 = (n_out + 3) / 4;
    zero_counts_kernel<<<(z4 + 255) / 256, 256>>>(z4);
    count_kernel<<<(total_idx + 255) / 256, 256>>>(out_index, total_idx);
    cond_bias_init_kernel<<<(n_out + 255) / 256, 256>>>(
        (const float4*)bias, (float4*)out, n_out);

    const int smem_bytes = (TILE_N * LDA + 2 * COUT * LDA) * sizeof(float); // ~68KB
    cudaFuncSetAttribute(spconvt_mma_kernel,
                         cudaFuncAttributeMaxDynamicSharedMemorySize, smem_bytes);
    dim3 grid((N + TILE_N - 1) / TILE_N, (KV + KCHUNK - 1) / KCHUNK);
    spconvt_mma_kernel<<<grid, 128, smem_bytes>>>(feats, weight, bias, out_index,
                                                  out, N, KV);
}